// round 1
// baseline (speedup 1.0000x reference)
#include <cuda_runtime.h>
#include <mma.h>
#include <cstdint>
#include <cstddef>

using namespace nvcuda;

// ---------------- problem dims ----------------
#define NQ   4096      // target rows
#define MKV  4096      // source rows
#define RD   144       // region dim
#define LD   3584      // llm dim
#define NH   4         // heads
#define HDIM 36        // head dim
#define HPAD 40        // padded head dim (mult of 8 for wmma k)
#define VHD  896       // value head dim

// ---------------- scratch (static device memory; no allocations allowed) ----------------
__device__ __align__(16) float g_Q   [NQ * RD];            // Q projection   [4096,144]
__device__ __align__(16) float g_K   [MKV * RD];           // K projection   [4096,144]
__device__ __align__(16) float g_Qp  [NH * NQ * HPAD];     // padded Q       [4][4096][40]
__device__ __align__(16) float g_Kp  [NH * HPAD * MKV];    // padded K^T     [4][40][4096]
__device__ __align__(16) float g_Bv  [LD * LD];            // packed wv      [3584,3584]
__device__ __align__(16) float g_bv  [LD];                 // packed wv bias
__device__ __align__(16) float g_V   [MKV * LD];           // projected V    [4096,3584]
__device__ __align__(16) float g_S   [NH * NQ * MKV];      // scores / probs [4][4096][4096] (268MB)
__device__ __align__(16) float g_X   [NQ * LD];            // pre-LN         [4096,3584]
__device__ __align__(16) float g_Y   [NQ * LD];            // post-LN        [4096,3584]

// ---------------- generic tf32 WMMA GEMM ----------------
// C[M,N] = alpha * A[M,K] @ B[K,N]  (+ bias[n]) (+ C_old if acc)
// Row-major A (lda), row-major B (ldb), row-major C (ldc). Batched via blockIdx.z strides.
constexpr int BM = 128, BN = 128, BK = 32;
constexpr int LDAS = BK + 8;   // 40   (smem A:  [BM][LDAS], m-major)
constexpr int LDBS = BN + 8;   // 136  (smem B:  [BK][LDBS], k-major)
constexpr int SMEM_FLOATS = 2 * BM * LDAS + 2 * BK * LDBS;   // 10240 + 8704 = 18944
constexpr int SMEM_BYTES  = SMEM_FLOATS * 4;                 // 75776 (> 48KB -> opt-in)
// C staging reuses smem: needs BM*LDBS = 17408 floats <= 18944. OK.

__device__ __forceinline__ void gload(const float* __restrict__ A, const float* __restrict__ B,
                                      int m0, int n0, int kbase,
                                      int M, int N, int K, int lda, int ldb, int tid,
                                      float4* ra, float4* rb)
{
#pragma unroll
    for (int i = 0; i < 4; i++) {
        int f  = tid + (i << 8);
        // A tile: 128 rows x 32 k, float4 along k
        int r  = f >> 3, k = (f & 7) << 2;
        int gm = m0 + r, gk = kbase + k;
        float4 v = make_float4(0.f, 0.f, 0.f, 0.f);
        if (gm < M && gk < K)
            v = *reinterpret_cast<const float4*>(A + (size_t)gm * lda + gk);
        ra[i] = v;
        // B tile: 32 k-rows x 128 n, float4 along n
        int kr = f >> 5, n = (f & 31) << 2;
        int gkr = kbase + kr, gn = n0 + n;
        float4 w = make_float4(0.f, 0.f, 0.f, 0.f);
        if (gkr < K && gn < N)
            w = *reinterpret_cast<const float4*>(B + (size_t)gkr * ldb + gn);
        rb[i] = w;
    }
}

__device__ __forceinline__ void sstore(float* as, float* bs, int tid,
                                       const float4* ra, const float4* rb)
{
#pragma unroll
    for (int i = 0; i < 4; i++) {
        int f = tid + (i << 8);
        int r = f >> 3, k = (f & 7) << 2;
        float4 v = ra[i];
        v.x = wmma::__float_to_tf32(v.x);
        v.y = wmma::__float_to_tf32(v.y);
        v.z = wmma::__float_to_tf32(v.z);
        v.w = wmma::__float_to_tf32(v.w);
        *reinterpret_cast<float4*>(as + r * LDAS + k) = v;
        int kr = f >> 5, n = (f & 31) << 2;
        float4 w = rb[i];
        w.x = wmma::__float_to_tf32(w.x);
        w.y = wmma::__float_to_tf32(w.y);
        w.z = wmma::__float_to_tf32(w.z);
        w.w = wmma::__float_to_tf32(w.w);
        *reinterpret_cast<float4*>(bs + kr * LDBS + n) = w;
    }
}

__global__ __launch_bounds__(256)
void gemm_tf32(const float* __restrict__ A, const float* __restrict__ B,
               float* __restrict__ C, const float* __restrict__ bias,
               int M, int N, int K, int lda, int ldb, int ldc,
               long long sA, long long sB, long long sC,
               float alpha, int acc)
{
    extern __shared__ float smem[];
    float* As = smem;
    float* Bs = smem + 2 * BM * LDAS;

    const int tid  = threadIdx.x;
    const int warp = tid >> 5;
    const int wm   = warp & 1;    // 2 warp-rows of 64
    const int wn   = warp >> 1;   // 4 warp-cols of 32
    const int m0   = blockIdx.y * BM;
    const int n0   = blockIdx.x * BN;

    A += (size_t)blockIdx.z * sA;
    B += (size_t)blockIdx.z * sB;
    C += (size_t)blockIdx.z * sC;

    wmma::fragment<wmma::accumulator, 16, 16, 8, float> cf[4][2];
#pragma unroll
    for (int i = 0; i < 4; i++)
#pragma unroll
        for (int j = 0; j < 2; j++)
            wmma::fill_fragment(cf[i][j], 0.f);

    const int KT = (K + BK - 1) / BK;
    float4 ra[4], rb[4];

    gload(A, B, m0, n0, 0, M, N, K, lda, ldb, tid, ra, rb);
    sstore(As, Bs, tid, ra, rb);
    __syncthreads();

    for (int kt = 0; kt < KT; kt++) {
        const int cur = kt & 1;
        if (kt + 1 < KT)
            gload(A, B, m0, n0, (kt + 1) * BK, M, N, K, lda, ldb, tid, ra, rb);

        const float* ap = As + cur * BM * LDAS;
        const float* bp = Bs + cur * BK * LDBS;
#pragma unroll
        for (int ks = 0; ks < 4; ks++) {
            wmma::fragment<wmma::matrix_a, 16, 16, 8, wmma::precision::tf32, wmma::row_major> af[4];
            wmma::fragment<wmma::matrix_b, 16, 16, 8, wmma::precision::tf32, wmma::row_major> bf[2];
#pragma unroll
            for (int i = 0; i < 4; i++)
                wmma::load_matrix_sync(af[i], ap + (wm * 64 + i * 16) * LDAS + ks * 8, LDAS);
#pragma unroll
            for (int j = 0; j < 2; j++)
                wmma::load_matrix_sync(bf[j], bp + (ks * 8) * LDBS + wn * 32 + j * 16, LDBS);
#pragma unroll
            for (int i = 0; i < 4; i++)
#pragma unroll
                for (int j = 0; j < 2; j++)
                    wmma::mma_sync(cf[i][j], af[i], bf[j], cf[i][j]);
        }
        if (kt + 1 < KT)
            sstore(As + (cur ^ 1) * BM * LDAS, Bs + (cur ^ 1) * BK * LDBS, tid, ra, rb);
        __syncthreads();
    }

    // epilogue: stage C in smem (reuse), then guarded global store with alpha/bias/acc
    float* Cs = smem;
#pragma unroll
    for (int i = 0; i < 4; i++)
#pragma unroll
        for (int j = 0; j < 2; j++)
            wmma::store_matrix_sync(Cs + (wm * 64 + i * 16) * LDBS + wn * 32 + j * 16,
                                    cf[i][j], LDBS, wmma::mem_row_major);
    __syncthreads();
    for (int e = tid; e < BM * BN; e += 256) {
        int m = e >> 7, n = e & 127;
        int gm = m0 + m, gn = n0 + n;
        if (gm < M && gn < N) {
            float v = Cs[m * LDBS + n] * alpha;
            if (bias) v += bias[gn];
            float* cp = C + (size_t)gm * ldc + gn;
            if (acc) v += *cp;
            *cp = v;
        }
    }
}

// ---------------- repack: stacked per-head V weights -> [3584,3584], bias -> [3584] ----------------
__global__ void pack_v_k(const float* __restrict__ wv, const float* __restrict__ wvb,
                         float* __restrict__ Bv, float* __restrict__ bv)
{
    int idx = blockIdx.x * 256 + threadIdx.x;
    if (idx >= LD * LD) return;
    int k = idx / LD, n = idx % LD;
    int h = n / VHD, d = n % VHD;
    Bv[idx] = wv[((size_t)h * LD + k) * VHD + d];
    if (k == 0) bv[n] = wvb[h * VHD + d];
}

// ---------------- pad head dim 36->40; build Q [h][n][40] and K^T [h][40][m] ----------------
__global__ void pad_qk_k(const float* __restrict__ Q, const float* __restrict__ Ks,
                         float* __restrict__ Qp, float* __restrict__ Kp)
{
    int idx = blockIdx.x * 256 + threadIdx.x;
    if (idx >= NH * NQ * HPAD) return;
    int k = idx % HPAD;
    int n = (idx / HPAD) % NQ;
    int h = idx / (HPAD * NQ);
    float q = 0.f, kk = 0.f;
    if (k < HDIM) {
        q  = Q [n * RD + h * HDIM + k];
        kk = Ks[n * RD + h * HDIM + k];
    }
    Qp[idx] = q;                                   // [h][n][k]
    Kp[((size_t)h * HPAD + k) * MKV + n] = kk;     // [h][k][m]
}

// ---------------- row softmax over 4096, in place ----------------
__global__ void softmax_k(float* __restrict__ S)
{
    const int row = blockIdx.x;
    const int h   = blockIdx.y;
    float* p = S + ((size_t)(h * NQ + row)) * MKV;
    const int tid = threadIdx.x;

    float x[16];
#pragma unroll
    for (int i = 0; i < 16; i++) x[i] = p[tid + (i << 8)];

    float mx = -1e30f;
#pragma unroll
    for (int i = 0; i < 16; i++) mx = fmaxf(mx, x[i]);
#pragma unroll
    for (int o = 16; o > 0; o >>= 1) mx = fmaxf(mx, __shfl_xor_sync(0xffffffffu, mx, o));
    __shared__ float rmax[8], rsum[8];
    if ((tid & 31) == 0) rmax[tid >> 5] = mx;
    __syncthreads();
    mx = rmax[0];
#pragma unroll
    for (int i = 1; i < 8; i++) mx = fmaxf(mx, rmax[i]);

    float s = 0.f, e[16];
#pragma unroll
    for (int i = 0; i < 16; i++) { e[i] = __expf(x[i] - mx); s += e[i]; }
#pragma unroll
    for (int o = 16; o > 0; o >>= 1) s += __shfl_xor_sync(0xffffffffu, s, o);
    if ((tid & 31) == 0) rsum[tid >> 5] = s;
    __syncthreads();
    s = rsum[0];
#pragma unroll
    for (int i = 1; i < 8; i++) s += rsum[i];

    const float inv = 1.f / s;
#pragma unroll
    for (int i = 0; i < 16; i++) p[tid + (i << 8)] = e[i] * inv;
}

// ---------------- LayerNorm over 3584 ----------------
__global__ void ln_k(const float* __restrict__ X, float* __restrict__ Y,
                     const float* __restrict__ g, const float* __restrict__ b)
{
    const int row = blockIdx.x;
    const float* xr = X + (size_t)row * LD;
    float*       yr = Y + (size_t)row * LD;
    const int tid = threadIdx.x;

    float x[14];
#pragma unroll
    for (int i = 0; i < 14; i++) x[i] = xr[tid + (i << 8)];

    float s = 0.f;
#pragma unroll
    for (int i = 0; i < 14; i++) s += x[i];
#pragma unroll
    for (int o = 16; o > 0; o >>= 1) s += __shfl_xor_sync(0xffffffffu, s, o);
    __shared__ float r1[8], r2[8];
    if ((tid & 31) == 0) r1[tid >> 5] = s;
    __syncthreads();
    s = 0.f;
#pragma unroll
    for (int i = 0; i < 8; i++) s += r1[i];
    const float mu = s * (1.f / LD);

    float vs = 0.f;
#pragma unroll
    for (int i = 0; i < 14; i++) { float d = x[i] - mu; vs += d * d; }
#pragma unroll
    for (int o = 16; o > 0; o >>= 1) vs += __shfl_xor_sync(0xffffffffu, vs, o);
    if ((tid & 31) == 0) r2[tid >> 5] = vs;
    __syncthreads();
    vs = 0.f;
#pragma unroll
    for (int i = 0; i < 8; i++) vs += r2[i];
    const float inv = rsqrtf(vs * (1.f / LD) + 1e-5f);

#pragma unroll
    for (int i = 0; i < 14; i++) {
        int c = tid + (i << 8);
        yr[c] = (x[i] - mu) * inv * g[c] + b[c];
    }
}

// ---------------- host-side launcher ----------------
static inline void launch_gemm(const float* A, const float* B, float* C, const float* bias,
                               int M, int N, int K, int lda, int ldb, int ldc,
                               long long sA, long long sB, long long sC, int batch,
                               float alpha, int acc)
{
    dim3 grid((N + BN - 1) / BN, (M + BM - 1) / BM, batch);
    gemm_tf32<<<grid, 256, SMEM_BYTES>>>(A, B, C, bias, M, N, K, lda, ldb, ldc,
                                         sA, sB, sC, alpha, acc);
}

extern "C" void kernel_launch(void* const* d_in, const int* in_sizes, int n_in,
                              void* d_out, int out_size)
{
    (void)in_sizes; (void)n_in; (void)out_size;
    const float* target  = (const float*)d_in[0];
    const float* source  = (const float*)d_in[1];
    const float* value   = (const float*)d_in[2];
    const float* wq_w    = (const float*)d_in[3];
    const float* wq_b    = (const float*)d_in[4];
    const float* wk_w    = (const float*)d_in[5];
    const float* wk_b    = (const float*)d_in[6];
    const float* wv_w    = (const float*)d_in[7];
    const float* wv_b    = (const float*)d_in[8];
    const float* resid_w = (const float*)d_in[9];
    const float* resid_b = (const float*)d_in[10];
    const float* out_w   = (const float*)d_in[11];
    const float* out_b   = (const float*)d_in[12];
    const float* ln_g    = (const float*)d_in[13];
    const float* ln_b    = (const float*)d_in[14];
    float* out = (float*)d_out;

    cudaFuncSetAttribute((const void*)gemm_tf32,
                         cudaFuncAttributeMaxDynamicSharedMemorySize, SMEM_BYTES);

    float *pQ, *pK, *pQp, *pKp, *pBv, *pbv, *pV, *pS, *pX, *pY;
    cudaGetSymbolAddress((void**)&pQ,  g_Q);
    cudaGetSymbolAddress((void**)&pK,  g_K);
    cudaGetSymbolAddress((void**)&pQp, g_Qp);
    cudaGetSymbolAddress((void**)&pKp, g_Kp);
    cudaGetSymbolAddress((void**)&pBv, g_Bv);
    cudaGetSymbolAddress((void**)&pbv, g_bv);
    cudaGetSymbolAddress((void**)&pV,  g_V);
    cudaGetSymbolAddress((void**)&pS,  g_S);
    cudaGetSymbolAddress((void**)&pX,  g_X);
    cudaGetSymbolAddress((void**)&pY,  g_Y);

    // 1) pack per-head V weights into one [3584,3584] matrix + bias
    pack_v_k<<<(LD * LD + 255) / 256, 256>>>(wv_w, wv_b, pBv, pbv);

    // 2) Q = target @ wq_w + wq_b          [4096,144]
    launch_gemm(target, wq_w, pQ, wq_b, NQ, RD, RD, RD, RD, RD, 0, 0, 0, 1, 1.f, 0);

    // 3) K = source @ wk_w + wk_b          [4096,144]
    launch_gemm(source, wk_w, pK, wk_b, MKV, RD, LD, LD, RD, RD, 0, 0, 0, 1, 1.f, 0);

    // 4) pad + transpose per head
    pad_qk_k<<<(NH * NQ * HPAD + 255) / 256, 256>>>(pQ, pK, pQp, pKp);

    // 5) scores[h] = (Qp[h] @ Kp[h]) / 6   [4][4096][4096]
    launch_gemm(pQp, pKp, pS, nullptr, NQ, MKV, HPAD,
                HPAD, MKV, MKV,
                (long long)NQ * HPAD, (long long)HPAD * MKV, (long long)NQ * MKV,
                NH, 1.f / 6.f, 0);

    // 6) softmax rows (in place)
    softmax_k<<<dim3(NQ, NH), 256>>>(pS);

    // 7) V = value @ Bv + bv               [4096,3584]
    launch_gemm(value, pBv, pV, pbv, MKV, LD, LD, LD, LD, LD, 0, 0, 0, 1, 1.f, 0);

    // 8) ctx[h] = P[h] @ V[:, h*896 : (h+1)*896]  -> X columns h*896..  (no bias)
    launch_gemm(pS, pV, pX, nullptr, NQ, VHD, MKV,
                MKV, LD, LD,
                (long long)NQ * MKV, (long long)VHD, (long long)VHD,
                NH, 1.f, 0);

    // 9) X += target @ resid_w + resid_b
    launch_gemm(target, resid_w, pX, resid_b, NQ, LD, RD, RD, LD, LD, 0, 0, 0, 1, 1.f, 1);

    // 10) Y = LayerNorm(X) * g + b
    ln_k<<<NQ, 256>>>(pX, pY, ln_g, ln_b);

    // 11) out = Y @ out_w + out_b
    launch_gemm(pY, out_w, out, out_b, NQ, LD, LD, LD, LD, LD, 0, 0, 0, 1, 1.f, 0);
}

// round 3
// speedup vs baseline: 1.6029x; 1.6029x over previous
#include <cuda_runtime.h>
#include <mma.h>
#include <cstdint>
#include <cstddef>

using namespace nvcuda;

// ---------------- problem dims ----------------
#define NQ   4096
#define MKV  4096
#define RD   144
#define LD   3584
#define NH   4
#define HDIM 36
#define HPAD 40
#define VHD  896

// ---------------- scratch ----------------
__device__ __align__(16) float g_Q   [NQ * RD];
__device__ __align__(16) float g_K   [MKV * RD];
__device__ __align__(16) float g_Qp  [NH * NQ * HPAD];
__device__ __align__(16) float g_Kp  [NH * HPAD * MKV];
__device__ __align__(16) float g_Bv  [LD * LD];
__device__ __align__(16) float g_bv  [LD];
__device__ __align__(16) float g_V   [MKV * LD];
__device__ __align__(16) float g_S   [(size_t)NH * NQ * MKV];
__device__ __align__(16) float g_X   [NQ * LD];
__device__ __align__(16) float g_Y   [NQ * LD];

// ---------------- cp.async helpers ----------------
__device__ __forceinline__ uint32_t smem_u32(const void* p) {
    uint32_t a;
    asm("{ .reg .u64 t; cvta.to.shared.u64 t, %1; cvt.u32.u64 %0, t; }" : "=r"(a) : "l"(p));
    return a;
}
__device__ __forceinline__ void cp16(uint32_t dst, const void* src, int nbytes) {
    asm volatile("cp.async.cg.shared.global [%0], [%1], 16, %2;"
                 :: "r"(dst), "l"(src), "r"(nbytes) : "memory");
}
#define CP_COMMIT() asm volatile("cp.async.commit_group;" ::: "memory")
#define CP_WAIT(n)  asm volatile("cp.async.wait_group %0;" :: "n"(n) : "memory")

// ---------------- tf32 WMMA GEMM, 128x128x32 tile, 4 warps (64x64 each) ----------------
// C[M,N] = alpha * A[M,K] @ B[K,N] (+ bias[n]) (+ C if acc). Row-major everywhere.
// M % 128 == 0; N, K multiples of 4. Batched via blockIdx.z.
constexpr int BM = 128, BN = 128, BK = 32;
constexpr int LDAS = BK + 8;   // 40
constexpr int LDBS = BN + 8;   // 136
constexpr int ASTG = BM * LDAS;        // 5120 floats
constexpr int BSTG = BK * LDBS;        // 4352 floats
constexpr int SMEM_FLOATS = 2 * ASTG + 2 * BSTG;   // 18944
constexpr int SMEM_BYTES  = SMEM_FLOATS * 4;       // 75776

__device__ __forceinline__ void load_stage(const float* __restrict__ A,
                                           const float* __restrict__ B,
                                           uint32_t sa, uint32_t sbb,
                                           int m0, int n0, int kbase,
                                           int N, int K, int lda, int ldb, int tid)
{
    // A tile: 128 rows x 32 floats (8 float4/row). 1024 float4s / 128 thr = 8 each.
#pragma unroll
    for (int i = 0; i < 8; i++) {
        int f = tid + i * 128;
        int r = f >> 3, c = f & 7;
        int gk = kbase + c * 4;
        const float* src = A + (size_t)(m0 + r) * lda + (gk < K ? gk : K - 4);
        int nb = (gk < K) ? 16 : 0;
        cp16(sa + (r * LDAS + c * 4) * 4, src, nb);
    }
    // B tile: 32 k-rows x 128 floats (32 float4/row).
#pragma unroll
    for (int i = 0; i < 8; i++) {
        int f = tid + i * 128;
        int kr = f >> 5, c = f & 31;
        int gk = kbase + kr;
        int gn = n0 + c * 4;
        const float* src = B + (size_t)(gk < K ? gk : K - 1) * ldb + (gn < N ? gn : 0);
        int nb = (gk < K && gn < N) ? 16 : 0;
        cp16(sbb + (kr * LDBS + c * 4) * 4, src, nb);
    }
}

__global__ __launch_bounds__(128, 2)
void gemm_tf32(const float* __restrict__ A, const float* __restrict__ B,
               float* __restrict__ C, const float* __restrict__ bias,
               int M, int N, int K, int lda, int ldb, int ldc,
               long long sA, long long sB, long long sC,
               float alpha, int acc)
{
    extern __shared__ float smem[];
    float* As = smem;
    float* Bs = smem + 2 * ASTG;
    const uint32_t sa_u = smem_u32(As);
    const uint32_t sb_u = smem_u32(Bs);

    const int tid  = threadIdx.x;
    const int warp = tid >> 5;
    const int wm   = warp & 1;    // 2 warp-rows of 64
    const int wn   = warp >> 1;   // 2 warp-cols of 64
    const int m0   = blockIdx.y * BM;
    const int n0   = blockIdx.x * BN;

    A += (size_t)blockIdx.z * sA;
    B += (size_t)blockIdx.z * sB;
    C += (size_t)blockIdx.z * sC;

    wmma::fragment<wmma::accumulator, 16, 16, 8, float> cf[4][4];
#pragma unroll
    for (int i = 0; i < 4; i++)
#pragma unroll
        for (int j = 0; j < 4; j++)
            wmma::fill_fragment(cf[i][j], 0.f);

    const int KT = (K + BK - 1) / BK;

    load_stage(A, B, sa_u, sb_u, m0, n0, 0, N, K, lda, ldb, tid);
    CP_COMMIT();

#pragma unroll 1
    for (int kt = 0; kt < KT; kt++) {
        const int cur = kt & 1;
        if (kt + 1 < KT) {
            load_stage(A, B, sa_u + (cur ^ 1) * ASTG * 4, sb_u + (cur ^ 1) * BSTG * 4,
                       m0, n0, (kt + 1) * BK, N, K, lda, ldb, tid);
            CP_COMMIT();
            CP_WAIT(1);
        } else {
            CP_WAIT(0);
        }
        __syncthreads();

        const float* ap = As + cur * ASTG + wm * 64 * LDAS;
        const float* bp = Bs + cur * BSTG + wn * 64;
#pragma unroll
        for (int ks = 0; ks < 4; ks++) {
            wmma::fragment<wmma::matrix_a, 16, 16, 8, wmma::precision::tf32, wmma::row_major> af[4];
            wmma::fragment<wmma::matrix_b, 16, 16, 8, wmma::precision::tf32, wmma::row_major> bf[4];
#pragma unroll
            for (int i = 0; i < 4; i++)
                wmma::load_matrix_sync(af[i], ap + (i * 16) * LDAS + ks * 8, LDAS);
#pragma unroll
            for (int j = 0; j < 4; j++)
                wmma::load_matrix_sync(bf[j], bp + (ks * 8) * LDBS + j * 16, LDBS);
#pragma unroll
            for (int i = 0; i < 4; i++)
#pragma unroll
                for (int j = 0; j < 4; j++)
                    wmma::mma_sync(cf[i][j], af[i], bf[j], cf[i][j]);
        }
        __syncthreads();
    }

    // epilogue: stage C in smem, then coalesced guarded float4 stores
    float* Cs = smem;   // 128 x LDBS floats = 17408 <= 18944
#pragma unroll
    for (int i = 0; i < 4; i++)
#pragma unroll
        for (int j = 0; j < 4; j++)
            wmma::store_matrix_sync(Cs + (wm * 64 + i * 16) * LDBS + wn * 64 + j * 16,
                                    cf[i][j], LDBS, wmma::mem_row_major);
    __syncthreads();

#pragma unroll 1
    for (int e = tid; e < 128 * 32; e += 128) {
        int rr = e >> 5, c4 = (e & 31) << 2;
        int gm = m0 + rr, gn = n0 + c4;
        if (gn >= N) continue;
        float4 v = *reinterpret_cast<float4*>(&Cs[rr * LDBS + c4]);
        v.x *= alpha; v.y *= alpha; v.z *= alpha; v.w *= alpha;
        if (bias) {
            float4 bv = *reinterpret_cast<const float4*>(bias + gn);
            v.x += bv.x; v.y += bv.y; v.z += bv.z; v.w += bv.w;
        }
        float* cp = C + (size_t)gm * ldc + gn;
        if (acc) {
            float4 o = *reinterpret_cast<float4*>(cp);
            v.x += o.x; v.y += o.y; v.z += o.z; v.w += o.w;
        }
        *reinterpret_cast<float4*>(cp) = v;
    }
}

// ---------------- repack: stacked per-head V weights -> [3584,3584], bias -> [3584] ----------------
__global__ void pack_v_k(const float* __restrict__ wv, const float* __restrict__ wvb,
                         float* __restrict__ Bv, float* __restrict__ bv)
{
    int idx = blockIdx.x * 256 + threadIdx.x;
    if (idx >= LD * LD) return;
    int k = idx / LD, n = idx % LD;
    int h = n / VHD, d = n % VHD;
    Bv[idx] = wv[((size_t)h * LD + k) * VHD + d];
    if (k == 0) bv[n] = wvb[h * VHD + d];
}

// ---------------- pad head dim 36->40; build Q [h][n][40] and K^T [h][40][m] ----------------
__global__ void pad_qk_k(const float* __restrict__ Q, const float* __restrict__ Ks,
                         float* __restrict__ Qp, float* __restrict__ Kp)
{
    int idx = blockIdx.x * 256 + threadIdx.x;
    if (idx >= NH * NQ * HPAD) return;
    int k = idx % HPAD;
    int n = (idx / HPAD) % NQ;
    int h = idx / (HPAD * NQ);
    float q = 0.f, kk = 0.f;
    if (k < HDIM) {
        q  = Q [n * RD + h * HDIM + k];
        kk = Ks[n * RD + h * HDIM + k];
    }
    Qp[idx] = q;
    Kp[((size_t)h * HPAD + k) * MKV + n] = kk;
}

// ---------------- row softmax over 4096, in place ----------------
__global__ void softmax_k(float* __restrict__ S)
{
    const int row = blockIdx.x;
    const int h   = blockIdx.y;
    float* p = S + ((size_t)(h * NQ + row)) * MKV;
    const int tid = threadIdx.x;

    float x[16];
#pragma unroll
    for (int i = 0; i < 16; i++) x[i] = p[tid + (i << 8)];

    float mx = -1e30f;
#pragma unroll
    for (int i = 0; i < 16; i++) mx = fmaxf(mx, x[i]);
#pragma unroll
    for (int o = 16; o > 0; o >>= 1) mx = fmaxf(mx, __shfl_xor_sync(0xffffffffu, mx, o));
    __shared__ float rmax[8], rsum[8];
    if ((tid & 31) == 0) rmax[tid >> 5] = mx;
    __syncthreads();
    mx = rmax[0];
#pragma unroll
    for (int i = 1; i < 8; i++) mx = fmaxf(mx, rmax[i]);

    float s = 0.f, e[16];
#pragma unroll
    for (int i = 0; i < 16; i++) { e[i] = __expf(x[i] - mx); s += e[i]; }
#pragma unroll
    for (int o = 16; o > 0; o >>= 1) s += __shfl_xor_sync(0xffffffffu, s, o);
    if ((tid & 31) == 0) rsum[tid >> 5] = s;
    __syncthreads();
    s = rsum[0];
#pragma unroll
    for (int i = 1; i < 8; i++) s += rsum[i];

    const float inv = 1.f / s;
#pragma unroll
    for (int i = 0; i < 16; i++) p[tid + (i << 8)] = e[i] * inv;
}

// ---------------- LayerNorm over 3584 ----------------
__global__ void ln_k(const float* __restrict__ X, float* __restrict__ Y,
                     const float* __restrict__ g, const float* __restrict__ b)
{
    const int row = blockIdx.x;
    const float* xr = X + (size_t)row * LD;
    float*       yr = Y + (size_t)row * LD;
    const int tid = threadIdx.x;

    float x[14];
#pragma unroll
    for (int i = 0; i < 14; i++) x[i] = xr[tid + (i << 8)];

    float s = 0.f;
#pragma unroll
    for (int i = 0; i < 14; i++) s += x[i];
#pragma unroll
    for (int o = 16; o > 0; o >>= 1) s += __shfl_xor_sync(0xffffffffu, s, o);
    __shared__ float r1[8], r2[8];
    if ((tid & 31) == 0) r1[tid >> 5] = s;
    __syncthreads();
    s = 0.f;
#pragma unroll
    for (int i = 0; i < 8; i++) s += r1[i];
    const float mu = s * (1.f / LD);

    float vs = 0.f;
#pragma unroll
    for (int i = 0; i < 14; i++) { float d = x[i] - mu; vs += d * d; }
#pragma unroll
    for (int o = 16; o > 0; o >>= 1) vs += __shfl_xor_sync(0xffffffffu, vs, o);
    if ((tid & 31) == 0) r2[tid >> 5] = vs;
    __syncthreads();
    vs = 0.f;
#pragma unroll
    for (int i = 0; i < 8; i++) vs += r2[i];
    const float inv = rsqrtf(vs * (1.f / LD) + 1e-5f);

#pragma unroll
    for (int i = 0; i < 14; i++) {
        int c = tid + (i << 8);
        yr[c] = (x[i] - mu) * inv * g[c] + b[c];
    }
}

// ---------------- host launcher ----------------
static inline void launch_gemm(const float* A, const float* B, float* C, const float* bias,
                               int M, int N, int K, int lda, int ldb, int ldc,
                               long long sA, long long sB, long long sC, int batch,
                               float alpha, int acc)
{
    dim3 grid((N + BN - 1) / BN, M / BM, batch);
    gemm_tf32<<<grid, 128, SMEM_BYTES>>>(A, B, C, bias, M, N, K, lda, ldb, ldc,
                                         sA, sB, sC, alpha, acc);
}

extern "C" void kernel_launch(void* const* d_in, const int* in_sizes, int n_in,
                              void* d_out, int out_size)
{
    (void)in_sizes; (void)n_in; (void)out_size;
    const float* target  = (const float*)d_in[0];
    const float* source  = (const float*)d_in[1];
    const float* value   = (const float*)d_in[2];
    const float* wq_w    = (const float*)d_in[3];
    const float* wq_b    = (const float*)d_in[4];
    const float* wk_w    = (const float*)d_in[5];
    const float* wk_b    = (const float*)d_in[6];
    const float* wv_w    = (const float*)d_in[7];
    const float* wv_b    = (const float*)d_in[8];
    const float* resid_w = (const float*)d_in[9];
    const float* resid_b = (const float*)d_in[10];
    const float* out_w   = (const float*)d_in[11];
    const float* out_b   = (const float*)d_in[12];
    const float* ln_g    = (const float*)d_in[13];
    const float* ln_b    = (const float*)d_in[14];
    float* out = (float*)d_out;

    cudaFuncSetAttribute((const void*)gemm_tf32,
                         cudaFuncAttributeMaxDynamicSharedMemorySize, SMEM_BYTES);

    float *pQ, *pK, *pQp, *pKp, *pBv, *pbv, *pV, *pS, *pX, *pY;
    cudaGetSymbolAddress((void**)&pQ,  g_Q);
    cudaGetSymbolAddress((void**)&pK,  g_K);
    cudaGetSymbolAddress((void**)&pQp, g_Qp);
    cudaGetSymbolAddress((void**)&pKp, g_Kp);
    cudaGetSymbolAddress((void**)&pBv, g_Bv);
    cudaGetSymbolAddress((void**)&pbv, g_bv);
    cudaGetSymbolAddress((void**)&pV,  g_V);
    cudaGetSymbolAddress((void**)&pS,  g_S);
    cudaGetSymbolAddress((void**)&pX,  g_X);
    cudaGetSymbolAddress((void**)&pY,  g_Y);

    // 1) pack per-head V weights
    pack_v_k<<<(LD * LD + 255) / 256, 256>>>(wv_w, wv_b, pBv, pbv);

    // 2) Q = target @ wq_w + wq_b          [4096,144]
    launch_gemm(target, wq_w, pQ, wq_b, NQ, RD, RD, RD, RD, RD, 0, 0, 0, 1, 1.f, 0);

    // 3) K = source @ wk_w + wk_b          [4096,144]
    launch_gemm(source, wk_w, pK, wk_b, MKV, RD, LD, LD, RD, RD, 0, 0, 0, 1, 1.f, 0);

    // 4) pad + transpose per head
    pad_qk_k<<<(NH * NQ * HPAD + 255) / 256, 256>>>(pQ, pK, pQp, pKp);

    // 5) scores[h] = (Qp[h] @ Kp[h]) / 6   [4][4096][4096]
    launch_gemm(pQp, pKp, pS, nullptr, NQ, MKV, HPAD,
                HPAD, MKV, MKV,
                (long long)NQ * HPAD, (long long)HPAD * MKV, (long long)NQ * MKV,
                NH, 1.f / 6.f, 0);

    // 6) softmax rows (in place)
    softmax_k<<<dim3(NQ, NH), 256>>>(pS);

    // 7) V = value @ Bv + bv               [4096,3584]
    launch_gemm(value, pBv, pV, pbv, MKV, LD, LD, LD, LD, LD, 0, 0, 0, 1, 1.f, 0);

    // 8) ctx[h] = P[h] @ V[:, h*896:(h+1)*896]
    launch_gemm(pS, pV, pX, nullptr, NQ, VHD, MKV,
                MKV, LD, LD,
                (long long)NQ * MKV, (long long)VHD, (long long)VHD,
                NH, 1.f, 0);

    // 9) X += target @ resid_w + resid_b
    launch_gemm(target, resid_w, pX, resid_b, NQ, LD, RD, RD, LD, LD, 0, 0, 0, 1, 1.f, 1);

    // 10) LayerNorm
    ln_k<<<NQ, 256>>>(pX, pY, ln_g, ln_b);

    // 11) out = Y @ out_w + out_b
    launch_gemm(pY, out_w, out, out_b, NQ, LD, LD, LD, LD, LD, 0, 0, 0, 1, 1.f, 0);
}